// round 1
// baseline (speedup 1.0000x reference)
#include <cuda_runtime.h>
#include <math.h>

// ---------------- problem constants ----------------
#define N_R     2000
#define N_P     1512
#define MROWS   3512            // N_R + N_P
#define SIZE_R  3000
#define FUN_IN  5603
#define NB      8192            // batch of pairs
#define PROTEIN 1512

// d_out layout: e_r [2000,512] | e_p [1512,512] | output [8192,2] | flat [8192,8192]
#define E_P_OFF   1024000
#define OUT_OFF   1798144
#define FLAT_OFF  1814528

// ---------------- device scratch (no allocs allowed) ----------------
__device__ float g_h_att[MROWS * 2048];
__device__ float g_h_fun[MROWS * 4096];
__device__ float g_e[MROWS * 512];

// ---------------- SGEMM: C = act(A @ B + bias) ----------------
// A rows: row < split -> A0[row], else A1[row-split], both stride lda.
// MODE 0: gelu(exact) -> C[r*ldc + c]
// MODE 1: sigmoid     -> ebuf[r*512 + ecol + c] and d_out e_r/e_p regions
#define TM 128
#define TBK 8

template<int MODE>
__global__ void __launch_bounds__(256) sgemm_kernel(
    const float* __restrict__ A0, const float* __restrict__ A1, int split,
    int M, int N, int K, int lda,
    const float* __restrict__ B, const float* __restrict__ bias,
    float* __restrict__ C, int ldc,
    float* __restrict__ ebuf, float* __restrict__ dout, int ecol)
{
    __shared__ float As[TBK][TM];
    __shared__ float Bs[TBK][TM];

    const int tid = threadIdx.x;
    const int tx = tid & 15;
    const int ty = tid >> 4;
    const int rowBase = blockIdx.y * TM;
    const int colBase = blockIdx.x * TM;

    float acc[8][8];
#pragma unroll
    for (int i = 0; i < 8; i++)
#pragma unroll
        for (int j = 0; j < 8; j++) acc[i][j] = 0.0f;

    // A tile load mapping: 128 rows x 8 k; each thread 4 consecutive k of one row
    const int am = tid >> 1;
    const int ak = (tid & 1) * 4;
    // B tile load mapping: 8 rows x 128 cols; each thread one float4
    const int bk = tid >> 5;
    const int bc = (tid & 31) * 4;

    const int arow = rowBase + am;
    const float* Arow = 0;
    if (arow < M)
        Arow = (arow < split) ? (A0 + (size_t)arow * lda)
                              : (A1 + (size_t)(arow - split) * lda);

    for (int k0 = 0; k0 < K; k0 += TBK) {
#pragma unroll
        for (int i = 0; i < 4; i++) {
            int kk = ak + i;
            float v = 0.0f;
            if (Arow && (k0 + kk) < K) v = Arow[k0 + kk];
            As[kk][am] = v;
        }
        {
            float4 v = make_float4(0.f, 0.f, 0.f, 0.f);
            int krow = k0 + bk;
            if (krow < K)
                v = *(const float4*)(B + (size_t)krow * N + colBase + bc);
            *(float4*)&Bs[bk][bc] = v;
        }
        __syncthreads();

#pragma unroll
        for (int kk = 0; kk < TBK; kk++) {
            float a[8], b[8];
            float4 a0 = *(const float4*)&As[kk][ty * 4];
            float4 a1 = *(const float4*)&As[kk][64 + ty * 4];
            float4 b0 = *(const float4*)&Bs[kk][tx * 4];
            float4 b1 = *(const float4*)&Bs[kk][64 + tx * 4];
            a[0]=a0.x; a[1]=a0.y; a[2]=a0.z; a[3]=a0.w;
            a[4]=a1.x; a[5]=a1.y; a[6]=a1.z; a[7]=a1.w;
            b[0]=b0.x; b[1]=b0.y; b[2]=b0.z; b[3]=b0.w;
            b[4]=b1.x; b[5]=b1.y; b[6]=b1.z; b[7]=b1.w;
#pragma unroll
            for (int i = 0; i < 8; i++)
#pragma unroll
                for (int j = 0; j < 8; j++)
                    acc[i][j] = fmaf(a[i], b[j], acc[i][j]);
        }
        __syncthreads();
    }

#pragma unroll
    for (int i = 0; i < 8; i++) {
        int r = rowBase + ((i < 4) ? (ty * 4 + i) : (64 + ty * 4 + (i - 4)));
        if (r >= M) continue;
#pragma unroll
        for (int j = 0; j < 8; j++) {
            int c = colBase + ((j < 4) ? (tx * 4 + j) : (64 + tx * 4 + (j - 4)));
            if (c >= N) continue;
            float v = acc[i][j] + bias[c];
            if (MODE == 0) {
                // exact gelu
                v = 0.5f * v * (1.0f + erff(v * 0.70710678118654752f));
                C[(size_t)r * ldc + c] = v;
            } else {
                v = 1.0f / (1.0f + expf(-v));
                ebuf[(size_t)r * 512 + ecol + c] = v;
                if (r < N_R)
                    dout[(size_t)r * 512 + ecol + c] = v;
                else
                    dout[(size_t)E_P_OFF + (size_t)(r - N_R) * 512 + ecol + c] = v;
            }
        }
    }
}

// ---------------- pair kernel: gather + conv1/avgpool + conv2/maxpool + tanh + out GEMM ----------------
// smem layout (floats):
//   xp   [6][520]        3120   (padded input rows; real data rows 2,3; col offset +4, data cols 2..517)
//   h1p  [16][2][264]    8448   (padded pooled conv1; col offset +4, data cols 4..259)
//   sw2  [32][16][15]    7680
//   sw1  [16][15]         240
//   bred [16]              16
#define SM_XP    0
#define SM_H1P   3120
#define SM_SW2   (3120 + 8448)
#define SM_SW1   (3120 + 8448 + 7680)
#define SM_BRED  (3120 + 8448 + 7680 + 240)
#define SM_TOTAL (3120 + 8448 + 7680 + 240 + 16)

__global__ void __launch_bounds__(256) pair_kernel(
    const float* __restrict__ e, const int* __restrict__ idx,
    const float* __restrict__ w1, const float* __restrict__ b1,
    const float* __restrict__ w2, const float* __restrict__ b2,
    const float* __restrict__ Wout, const float* __restrict__ bout,
    float* __restrict__ dout)
{
    extern __shared__ float sm[];
    float* xp   = sm + SM_XP;    // [6][520]
    float* h1p  = sm + SM_H1P;   // [16][2][264]
    float* sw2  = sm + SM_SW2;   // [32][16][15]
    float* sw1  = sm + SM_SW1;   // [16][15]
    float* bred = sm + SM_BRED;  // [16]

    const int tid = threadIdx.x;
    const int b = blockIdx.x;

    const int iv = idx[b];
    const int rno = iv / PROTEIN;
    const int pno = iv % PROTEIN;
    const float* er = e + (size_t)rno * 512;
    const float* ep = e + (size_t)(N_R + pno) * 512;

    // zero padded tiles
    for (int i = tid; i < 6 * 520; i += 256) xp[i] = 0.0f;
    for (int i = tid; i < 16 * 2 * 264; i += 256) h1p[i] = 0.0f;
    // weights to smem
    for (int i = tid; i < 240; i += 256) sw1[i] = w1[i];
    for (int i = tid; i < 7680; i += 256) sw2[i] = w2[i];
    // gather input rows (x rows: 0 = e_r, 1 = e_p), stored at padded rows 2,3, col +4
    for (int w = tid; w < 512; w += 256) {
        xp[2 * 520 + 4 + w] = er[w];
        xp[3 * 520 + 4 + w] = ep[w];
    }
    __syncthreads();

    // ---- conv1 + leaky + avgpool, fused -> h1p[c][ph][4+pw] ----
    // pooled(c,ph,pw) = 0.25 * sum_{oh2,ow2} leaky(b1[c] + sum_{kh,kw} w1[c,kh,kw]*x[oh+kh-2, ow+kw-2])
    // padded: x row index (oh+kh-2)+2 = oh+kh ; col index (ow+kw-2)+4 = ow+kw+2
    for (int id = tid; id < 16 * 2 * 256; id += 256) {
        int c  = id >> 9;
        int rm = id & 511;
        int ph = rm >> 8;
        int pw = rm & 255;
        float wv[15];
#pragma unroll
        for (int q = 0; q < 15; q++) wv[q] = sw1[c * 15 + q];
        float bb = b1[c];
        float sum = 0.0f;
#pragma unroll
        for (int oh2 = 0; oh2 < 2; oh2++) {
#pragma unroll
            for (int ow2 = 0; ow2 < 2; ow2++) {
                int oh = 2 * ph + oh2;
                int ow = 2 * pw + ow2;
                float v = bb;
#pragma unroll
                for (int kh = 0; kh < 3; kh++) {
                    const float* xr = xp + (oh + kh) * 520 + (ow + 2);
#pragma unroll
                    for (int kw = 0; kw < 5; kw++)
                        v = fmaf(wv[kh * 5 + kw], xr[kw], v);
                }
                sum += (v >= 0.0f) ? v : 0.01f * v;
            }
        }
        h1p[(c * 2 + ph) * 264 + 4 + pw] = 0.25f * sum;
    }
    __syncthreads();

    // ---- conv2 + leaky + maxpool + tanh + flat write + W_out dot ----
    // 1024 tasks: (ocp 0..15, ph 0..1, pwg 0..31); each: oc in {2ocp,2ocp+1},
    // conv rows oh in {2ph,2ph+1}, conv cols ow in [8*pwg, 8*pwg+7]
    float a0 = 0.0f, a1 = 0.0f;

    for (int t = 0; t < 4; t++) {
        int task = t * 256 + tid;
        int ocp = task >> 6;
        int ph  = (task >> 5) & 1;
        int pwg = task & 31;
        int oc0 = ocp * 2;
        int w0 = pwg * 8;

        float acc[2][2][8];
#pragma unroll
        for (int o = 0; o < 2; o++)
#pragma unroll
            for (int r = 0; r < 2; r++)
#pragma unroll
                for (int j = 0; j < 8; j++) acc[o][r][j] = 0.0f;

        for (int ic = 0; ic < 16; ic++) {
#pragma unroll
            for (int kh = 0; kh < 3; kh++) {
                float wa[5], wb[5];
#pragma unroll
                for (int kw = 0; kw < 5; kw++) {
                    wa[kw] = sw2[(oc0 * 16 + ic) * 15 + kh * 5 + kw];
                    wb[kw] = sw2[((oc0 + 1) * 16 + ic) * 15 + kh * 5 + kw];
                }
#pragma unroll
                for (int rr = 0; rr < 2; rr++) {
                    int ih = 2 * ph + rr + kh - 2;
                    if (ih < 0 || ih > 1) continue;
                    const float* row = h1p + (ic * 2 + ih) * 264;
                    float hv[16];
                    float4 q0 = *(const float4*)(row + w0);
                    float4 q1 = *(const float4*)(row + w0 + 4);
                    float4 q2 = *(const float4*)(row + w0 + 8);
                    float4 q3 = *(const float4*)(row + w0 + 12);
                    hv[0]=q0.x; hv[1]=q0.y; hv[2]=q0.z; hv[3]=q0.w;
                    hv[4]=q1.x; hv[5]=q1.y; hv[6]=q1.z; hv[7]=q1.w;
                    hv[8]=q2.x; hv[9]=q2.y; hv[10]=q2.z; hv[11]=q2.w;
                    hv[12]=q3.x; hv[13]=q3.y; hv[14]=q3.z; hv[15]=q3.w;
                    // padded col of conv input (ow+kw-2)+4 = w0 + j + kw + 2
#pragma unroll
                    for (int j = 0; j < 8; j++) {
#pragma unroll
                        for (int kw = 0; kw < 5; kw++) {
                            float h = hv[2 + j + kw];
                            acc[0][rr][j] = fmaf(wa[kw], h, acc[0][rr][j]);
                            acc[1][rr][j] = fmaf(wb[kw], h, acc[1][rr][j]);
                        }
                    }
                }
            }
        }

        // epilogue: bias -> leaky -> 2x2 maxpool -> tanh; write flat; accumulate W_out dot
#pragma unroll
        for (int o = 0; o < 2; o++) {
            int oc = oc0 + o;
            float bb = b2[oc];
            int fibase = oc * 256 + ph * 128 + pwg * 4;
#pragma unroll
            for (int jp = 0; jp < 4; jp++) {
                float m = -3.4e38f;
#pragma unroll
                for (int rr = 0; rr < 2; rr++) {
#pragma unroll
                    for (int dj = 0; dj < 2; dj++) {
                        float v = acc[o][rr][jp * 2 + dj] + bb;
                        v = (v >= 0.0f) ? v : 0.01f * v;
                        m = fmaxf(m, v);
                    }
                }
                float fv = tanhf(m);
                int fi = fibase + jp;
                dout[(size_t)FLAT_OFF + (size_t)b * 8192 + fi] = fv;
                a0 = fmaf(fv, __ldg(&Wout[2 * fi]), a0);
                a1 = fmaf(fv, __ldg(&Wout[2 * fi + 1]), a1);
            }
        }
    }

    // block reduce (a0, a1)
#pragma unroll
    for (int off = 16; off > 0; off >>= 1) {
        a0 += __shfl_down_sync(0xFFFFFFFFu, a0, off);
        a1 += __shfl_down_sync(0xFFFFFFFFu, a1, off);
    }
    if ((tid & 31) == 0) {
        bred[(tid >> 5) * 2 + 0] = a0;
        bred[(tid >> 5) * 2 + 1] = a1;
    }
    __syncthreads();
    if (tid == 0) {
        float s0 = bout[0], s1 = bout[1];
#pragma unroll
        for (int w = 0; w < 8; w++) { s0 += bred[2 * w]; s1 += bred[2 * w + 1]; }
        dout[(size_t)OUT_OFF + (size_t)b * 2 + 0] = s0;
        dout[(size_t)OUT_OFF + (size_t)b * 2 + 1] = s1;
    }
}

// ---------------- launcher ----------------
extern "C" void kernel_launch(void* const* d_in, const int* in_sizes, int n_in,
                              void* d_out, int out_size)
{
    const float* r_att  = (const float*)d_in[0];
    const float* p_att  = (const float*)d_in[1];
    const float* r_fun  = (const float*)d_in[2];
    const float* p_fun  = (const float*)d_in[3];
    const int*   idx    = (const int*)  d_in[4];
    const float* W_att1 = (const float*)d_in[5];
    const float* b_att1 = (const float*)d_in[6];
    const float* W_att2 = (const float*)d_in[7];
    const float* b_att2 = (const float*)d_in[8];
    const float* W_fun1 = (const float*)d_in[9];
    const float* b_fun1 = (const float*)d_in[10];
    const float* W_fun2 = (const float*)d_in[11];
    const float* b_fun2 = (const float*)d_in[12];
    const float* conv1w = (const float*)d_in[13];
    const float* conv1b = (const float*)d_in[14];
    const float* conv2w = (const float*)d_in[15];
    const float* conv2b = (const float*)d_in[16];
    const float* W_out  = (const float*)d_in[17];
    const float* b_out  = (const float*)d_in[18];
    float* out = (float*)d_out;

    float *h_att, *h_fun, *e;
    cudaGetSymbolAddress((void**)&h_att, g_h_att);
    cudaGetSymbolAddress((void**)&h_fun, g_h_fun);
    cudaGetSymbolAddress((void**)&e,     g_e);

    const int mb = (MROWS + TM - 1) / TM;  // 28

    // G1: gelu(att @ W_att1 + b) -> h_att  [3512 x 2048], K=3000
    sgemm_kernel<0><<<dim3(2048 / TM, mb), 256>>>(
        r_att, p_att, N_R, MROWS, 2048, SIZE_R, SIZE_R,
        W_att1, b_att1, h_att, 2048, 0, 0, 0);

    // G2: sigmoid(h_att @ W_att2 + b) -> e[:, 0:256] and d_out e_r/e_p
    sgemm_kernel<1><<<dim3(256 / TM, mb), 256>>>(
        h_att, h_att, MROWS, MROWS, 256, 2048, 2048,
        W_att2, b_att2, 0, 0, e, out, 0);

    // G3: gelu(fun @ W_fun1 + b) -> h_fun  [3512 x 4096], K=5603
    sgemm_kernel<0><<<dim3(4096 / TM, mb), 256>>>(
        r_fun, p_fun, N_R, MROWS, 4096, FUN_IN, FUN_IN,
        W_fun1, b_fun1, h_fun, 4096, 0, 0, 0);

    // G4: sigmoid(h_fun @ W_fun2 + b) -> e[:, 256:512] and d_out e_r/e_p
    sgemm_kernel<1><<<dim3(256 / TM, mb), 256>>>(
        h_fun, h_fun, MROWS, MROWS, 256, 4096, 4096,
        W_fun2, b_fun2, 0, 0, e, out, 256);

    // pair head
    cudaFuncSetAttribute(pair_kernel,
        cudaFuncAttributeMaxDynamicSharedMemorySize, SM_TOTAL * 4);
    pair_kernel<<<NB, 256, SM_TOTAL * 4>>>(
        e, idx, conv1w, conv1b, conv2w, conv2b, W_out, b_out, out);
}

// round 3
// speedup vs baseline: 1.4977x; 1.4977x over previous
#include <cuda_runtime.h>
#include <math.h>
#include <stdint.h>

// ---------------- problem constants ----------------
#define N_R     2000
#define N_P     1512
#define MROWS   3512            // N_R + N_P
#define SIZE_R  3000
#define FUN_IN  5603
#define NB      8192            // batch of pairs
#define PROTEIN 1512

// d_out layout: e_r [2000,512] | e_p [1512,512] | output [8192,2] | flat [8192,8192]
#define E_P_OFF   1024000
#define OUT_OFF   1798144
#define FLAT_OFF  1814528

// ---------------- device scratch (no allocs allowed) ----------------
__device__ float g_h_att[MROWS * 2048];
__device__ float g_h_fun[MROWS * 4096];
__device__ float g_e[MROWS * 512];

// ---------------- tf32 helpers ----------------
__device__ __forceinline__ uint32_t f2tf(float x) {
    uint32_t r;
    asm("cvt.rna.tf32.f32 %0, %1;" : "=r"(r) : "f"(x));
    return r;
}

__device__ __forceinline__ void mma_tf32(float c[4],
    uint32_t a0, uint32_t a1, uint32_t a2, uint32_t a3,
    uint32_t b0, uint32_t b1)
{
    asm volatile(
        "mma.sync.aligned.m16n8k8.row.col.f32.tf32.tf32.f32 "
        "{%0,%1,%2,%3}, {%4,%5,%6,%7}, {%8,%9}, {%0,%1,%2,%3};\n"
        : "+f"(c[0]), "+f"(c[1]), "+f"(c[2]), "+f"(c[3])
        : "r"(a0), "r"(a1), "r"(a2), "r"(a3), "r"(b0), "r"(b1));
}

// ---------------- TF32 tensor-core GEMM: C = act(A @ B + bias) ----------------
// A rows: row < split -> A0[row], else A1[row-split], both stride lda.
// ALIGNED: lda % 4 == 0 -> float4 A loads; else scalar (misalignment-safe).
// MODE 0: gelu(exact) -> C[r*ldc + c]
// MODE 1: sigmoid     -> ebuf[r*512 + ecol + c] and d_out e_r/e_p regions
//
// CTA tile: BM x 128, BK=16. 256 threads = 8 warps, 2 rows x 4 cols,
// warp tile (BM/2) x 32. Each warp: MT=BM/32 m16 tiles x 4 n8 tiles per k8.
template<int BM, int MODE, bool ALIGNED>
__global__ void __launch_bounds__(256) mma_gemm(
    const float* __restrict__ A0, const float* __restrict__ A1, int split,
    int M, int N, int K, int lda,
    const float* __restrict__ B, const float* __restrict__ bias,
    float* __restrict__ C, int ldc,
    float* __restrict__ ebuf, float* __restrict__ dout, int ecol)
{
    constexpr int BN = 128;
    constexpr int BK = 16;
    constexpr int MT = BM / 32;                // m16 tiles per warp
    constexpr int AF = (BM * BK) / (4 * 256);  // float4-equivalent A loads per thread

    __shared__ uint32_t As[BM][20];    // [m][k], row stride 20: conflict-free frag loads
    __shared__ uint32_t Bs[BK][136];   // [k][n], row stride 136: conflict-free frag loads

    const int tid  = threadIdx.x;
    const int lane = tid & 31;
    const int warp = tid >> 5;
    const int wr = warp & 1;           // warp row (2)
    const int wc = warp >> 1;          // warp col (4)
    const int g = lane >> 2;           // group id 0..7
    const int t = lane & 3;            // thread-in-group 0..3

    const int rowBase = blockIdx.y * BM;
    const int colBase = blockIdx.x * BN;
    const int wm = wr * (BM / 2);      // warp m offset in tile
    const int wn = wc * 32;            // warp n offset in tile

    float acc[MT][4][4];
#pragma unroll
    for (int i = 0; i < MT; i++)
#pragma unroll
        for (int j = 0; j < 4; j++)
#pragma unroll
            for (int q = 0; q < 4; q++) acc[i][j][q] = 0.0f;

    // A-load mapping: chunk index f -> m = f>>2, kq = f&3 (k = 4*kq)
    // B-load mapping: chunk index f -> k = f>>5, nq = f&31
    const float* Arow[AF];
#pragma unroll
    for (int i = 0; i < AF; i++) {
        int f = tid + i * 256;
        int m = f >> 2;
        int row = rowBase + m;
        Arow[i] = 0;
        if (row < M)
            Arow[i] = (row < split) ? (A0 + (size_t)row * lda)
                                    : (A1 + (size_t)(row - split) * lda);
    }

    for (int k0 = 0; k0 < K; k0 += BK) {
        // ---- load A tile -> As[m][k] (tf32) ----
#pragma unroll
        for (int i = 0; i < AF; i++) {
            int f = tid + i * 256;
            int m = f >> 2;
            int kq = f & 3;
            int k = k0 + kq * 4;
            float4 v = make_float4(0.f, 0.f, 0.f, 0.f);
            if (Arow[i]) {
                if (ALIGNED && (k + 4 <= K)) {
                    v = *(const float4*)(Arow[i] + k);
                } else {
                    float tmp[4] = {0.f, 0.f, 0.f, 0.f};
#pragma unroll
                    for (int j = 0; j < 4; j++)
                        if (k + j < K) tmp[j] = __ldg(Arow[i] + k + j);
                    v = make_float4(tmp[0], tmp[1], tmp[2], tmp[3]);
                }
            }
            uint4 u;
            u.x = f2tf(v.x); u.y = f2tf(v.y); u.z = f2tf(v.z); u.w = f2tf(v.w);
            *(uint4*)&As[m][kq * 4] = u;
        }
        // ---- load B tile -> Bs[k][n] (tf32) ----
#pragma unroll
        for (int i = 0; i < 2; i++) {
            int f = tid + i * 256;
            int k = f >> 5;
            int nq = f & 31;
            float4 v = make_float4(0.f, 0.f, 0.f, 0.f);
            if (k0 + k < K)
                v = *(const float4*)(B + (size_t)(k0 + k) * N + colBase + nq * 4);
            uint4 u;
            u.x = f2tf(v.x); u.y = f2tf(v.y); u.z = f2tf(v.z); u.w = f2tf(v.w);
            *(uint4*)&Bs[k][nq * 4] = u;
        }
        __syncthreads();

        // ---- compute: 2 k8 steps ----
#pragma unroll
        for (int ks = 0; ks < 2; ks++) {
            uint32_t afr[MT][4];
            uint32_t bfr[4][2];
#pragma unroll
            for (int mt = 0; mt < MT; mt++) {
                int r0 = wm + mt * 16 + g;
                afr[mt][0] = As[r0][ks * 8 + t];
                afr[mt][1] = As[r0 + 8][ks * 8 + t];
                afr[mt][2] = As[r0][ks * 8 + t + 4];
                afr[mt][3] = As[r0 + 8][ks * 8 + t + 4];
            }
#pragma unroll
            for (int nt = 0; nt < 4; nt++) {
                int c0 = wn + nt * 8 + g;
                bfr[nt][0] = Bs[ks * 8 + t][c0];
                bfr[nt][1] = Bs[ks * 8 + t + 4][c0];
            }
#pragma unroll
            for (int mt = 0; mt < MT; mt++)
#pragma unroll
                for (int nt = 0; nt < 4; nt++)
                    mma_tf32(acc[mt][nt],
                             afr[mt][0], afr[mt][1], afr[mt][2], afr[mt][3],
                             bfr[nt][0], bfr[nt][1]);
        }
        __syncthreads();
    }

    // ---- epilogue ----
#pragma unroll
    for (int mt = 0; mt < MT; mt++) {
#pragma unroll
        for (int rh = 0; rh < 2; rh++) {
            int r = rowBase + wm + mt * 16 + g + rh * 8;
            if (r >= M) continue;
#pragma unroll
            for (int nt = 0; nt < 4; nt++) {
#pragma unroll
                for (int cj = 0; cj < 2; cj++) {
                    int c = colBase + wn + nt * 8 + 2 * t + cj;
                    if (c >= N) continue;
                    float v = acc[mt][nt][rh * 2 + cj] + bias[c];
                    if (MODE == 0) {
                        v = 0.5f * v * (1.0f + erff(v * 0.70710678118654752f));
                        C[(size_t)r * ldc + c] = v;
                    } else {
                        v = 1.0f / (1.0f + expf(-v));
                        ebuf[(size_t)r * 512 + ecol + c] = v;
                        if (r < N_R)
                            dout[(size_t)r * 512 + ecol + c] = v;
                        else
                            dout[(size_t)E_P_OFF + (size_t)(r - N_R) * 512 + ecol + c] = v;
                    }
                }
            }
        }
    }
}

// ---------------- pair kernel: gather + conv1/avgpool + conv2/maxpool + tanh + out GEMM ----------------
#define SM_XP    0
#define SM_H1P   3120
#define SM_SW2   (3120 + 8448)
#define SM_SW1   (3120 + 8448 + 7680)
#define SM_BRED  (3120 + 8448 + 7680 + 240)
#define SM_TOTAL (3120 + 8448 + 7680 + 240 + 16)

__global__ void __launch_bounds__(256) pair_kernel(
    const float* __restrict__ e, const int* __restrict__ idx,
    const float* __restrict__ w1, const float* __restrict__ b1,
    const float* __restrict__ w2, const float* __restrict__ b2,
    const float* __restrict__ Wout, const float* __restrict__ bout,
    float* __restrict__ dout)
{
    extern __shared__ float sm[];
    float* xp   = sm + SM_XP;    // [6][520]
    float* h1p  = sm + SM_H1P;   // [16][2][264]
    float* sw2  = sm + SM_SW2;   // [32][16][15]
    float* sw1  = sm + SM_SW1;   // [16][15]
    float* bred = sm + SM_BRED;  // [16]

    const int tid = threadIdx.x;
    const int b = blockIdx.x;

    const int iv = idx[b];
    const int rno = iv / PROTEIN;
    const int pno = iv % PROTEIN;
    const float* er = e + (size_t)rno * 512;
    const float* ep = e + (size_t)(N_R + pno) * 512;

    for (int i = tid; i < 6 * 520; i += 256) xp[i] = 0.0f;
    for (int i = tid; i < 16 * 2 * 264; i += 256) h1p[i] = 0.0f;
    for (int i = tid; i < 240; i += 256) sw1[i] = w1[i];
    for (int i = tid; i < 7680; i += 256) sw2[i] = w2[i];
    for (int w = tid; w < 512; w += 256) {
        xp[2 * 520 + 4 + w] = er[w];
        xp[3 * 520 + 4 + w] = ep[w];
    }
    __syncthreads();

    // conv1 + leaky + avgpool
    for (int id = tid; id < 16 * 2 * 256; id += 256) {
        int c  = id >> 9;
        int rm = id & 511;
        int ph = rm >> 8;
        int pw = rm & 255;
        float wv[15];
#pragma unroll
        for (int q = 0; q < 15; q++) wv[q] = sw1[c * 15 + q];
        float bb = b1[c];
        float sum = 0.0f;
#pragma unroll
        for (int oh2 = 0; oh2 < 2; oh2++) {
#pragma unroll
            for (int ow2 = 0; ow2 < 2; ow2++) {
                int oh = 2 * ph + oh2;
                int ow = 2 * pw + ow2;
                float v = bb;
#pragma unroll
                for (int kh = 0; kh < 3; kh++) {
                    const float* xr = xp + (oh + kh) * 520 + (ow + 2);
#pragma unroll
                    for (int kw = 0; kw < 5; kw++)
                        v = fmaf(wv[kh * 5 + kw], xr[kw], v);
                }
                sum += (v >= 0.0f) ? v : 0.01f * v;
            }
        }
        h1p[(c * 2 + ph) * 264 + 4 + pw] = 0.25f * sum;
    }
    __syncthreads();

    // conv2 + leaky + maxpool + tanh + flat + W_out dot
    float a0 = 0.0f, a1 = 0.0f;

    for (int tt = 0; tt < 4; tt++) {
        int task = tt * 256 + tid;
        int ocp = task >> 6;
        int ph  = (task >> 5) & 1;
        int pwg = task & 31;
        int oc0 = ocp * 2;
        int w0 = pwg * 8;

        float acc[2][2][8];
#pragma unroll
        for (int o = 0; o < 2; o++)
#pragma unroll
            for (int r = 0; r < 2; r++)
#pragma unroll
                for (int j = 0; j < 8; j++) acc[o][r][j] = 0.0f;

        for (int ic = 0; ic < 16; ic++) {
#pragma unroll
            for (int kh = 0; kh < 3; kh++) {
                float wa[5], wb[5];
#pragma unroll
                for (int kw = 0; kw < 5; kw++) {
                    wa[kw] = sw2[(oc0 * 16 + ic) * 15 + kh * 5 + kw];
                    wb[kw] = sw2[((oc0 + 1) * 16 + ic) * 15 + kh * 5 + kw];
                }
#pragma unroll
                for (int rr = 0; rr < 2; rr++) {
                    int ih = 2 * ph + rr + kh - 2;
                    if (ih < 0 || ih > 1) continue;
                    const float* row = h1p + (ic * 2 + ih) * 264;
                    float hv[16];
                    float4 q0 = *(const float4*)(row + w0);
                    float4 q1 = *(const float4*)(row + w0 + 4);
                    float4 q2 = *(const float4*)(row + w0 + 8);
                    float4 q3 = *(const float4*)(row + w0 + 12);
                    hv[0]=q0.x; hv[1]=q0.y; hv[2]=q0.z; hv[3]=q0.w;
                    hv[4]=q1.x; hv[5]=q1.y; hv[6]=q1.z; hv[7]=q1.w;
                    hv[8]=q2.x; hv[9]=q2.y; hv[10]=q2.z; hv[11]=q2.w;
                    hv[12]=q3.x; hv[13]=q3.y; hv[14]=q3.z; hv[15]=q3.w;
#pragma unroll
                    for (int j = 0; j < 8; j++) {
#pragma unroll
                        for (int kw = 0; kw < 5; kw++) {
                            float h = hv[2 + j + kw];
                            acc[0][rr][j] = fmaf(wa[kw], h, acc[0][rr][j]);
                            acc[1][rr][j] = fmaf(wb[kw], h, acc[1][rr][j]);
                        }
                    }
                }
            }
        }

#pragma unroll
        for (int o = 0; o < 2; o++) {
            int oc = oc0 + o;
            float bb = b2[oc];
            int fibase = oc * 256 + ph * 128 + pwg * 4;
#pragma unroll
            for (int jp = 0; jp < 4; jp++) {
                float m = -3.4e38f;
#pragma unroll
                for (int rr = 0; rr < 2; rr++) {
#pragma unroll
                    for (int dj = 0; dj < 2; dj++) {
                        float v = acc[o][rr][jp * 2 + dj] + bb;
                        v = (v >= 0.0f) ? v : 0.01f * v;
                        m = fmaxf(m, v);
                    }
                }
                float fv = tanhf(m);
                int fi = fibase + jp;
                dout[(size_t)FLAT_OFF + (size_t)b * 8192 + fi] = fv;
                a0 = fmaf(fv, __ldg(&Wout[2 * fi]), a0);
                a1 = fmaf(fv, __ldg(&Wout[2 * fi + 1]), a1);
            }
        }
    }

#pragma unroll
    for (int off = 16; off > 0; off >>= 1) {
        a0 += __shfl_down_sync(0xFFFFFFFFu, a0, off);
        a1 += __shfl_down_sync(0xFFFFFFFFu, a1, off);
    }
    if ((tid & 31) == 0) {
        bred[(tid >> 5) * 2 + 0] = a0;
        bred[(tid >> 5) * 2 + 1] = a1;
    }
    __syncthreads();
    if (tid == 0) {
        float s0 = bout[0], s1 = bout[1];
#pragma unroll
        for (int w = 0; w < 8; w++) { s0 += bred[2 * w]; s1 += bred[2 * w + 1]; }
        dout[(size_t)OUT_OFF + (size_t)b * 2 + 0] = s0;
        dout[(size_t)OUT_OFF + (size_t)b * 2 + 1] = s1;
    }
}

// ---------------- launcher ----------------
extern "C" void kernel_launch(void* const* d_in, const int* in_sizes, int n_in,
                              void* d_out, int out_size)
{
    const float* r_att  = (const float*)d_in[0];
    const float* p_att  = (const float*)d_in[1];
    const float* r_fun  = (const float*)d_in[2];
    const float* p_fun  = (const float*)d_in[3];
    const int*   idx    = (const int*)  d_in[4];
    const float* W_att1 = (const float*)d_in[5];
    const float* b_att1 = (const float*)d_in[6];
    const float* W_att2 = (const float*)d_in[7];
    const float* b_att2 = (const float*)d_in[8];
    const float* W_fun1 = (const float*)d_in[9];
    const float* b_fun1 = (const float*)d_in[10];
    const float* W_fun2 = (const float*)d_in[11];
    const float* b_fun2 = (const float*)d_in[12];
    const float* conv1w = (const float*)d_in[13];
    const float* conv1b = (const float*)d_in[14];
    const float* conv2w = (const float*)d_in[15];
    const float* conv2b = (const float*)d_in[16];
    const float* W_out  = (const float*)d_in[17];
    const float* b_out  = (const float*)d_in[18];
    float* out = (float*)d_out;

    float *h_att, *h_fun, *e;
    cudaGetSymbolAddress((void**)&h_att, g_h_att);
    cudaGetSymbolAddress((void**)&h_fun, g_h_fun);
    cudaGetSymbolAddress((void**)&e,     g_e);

    // G1: gelu(att @ W_att1 + b) -> h_att  [3512 x 2048], K=3000 (lda%4==0)
    mma_gemm<128, 0, true><<<dim3(2048 / 128, (MROWS + 127) / 128), 256>>>(
        r_att, p_att, N_R, MROWS, 2048, SIZE_R, SIZE_R,
        W_att1, b_att1, h_att, 2048, 0, 0, 0);

    // G3: gelu(fun @ W_fun1 + b) -> h_fun  [3512 x 4096], K=5603 (odd lda -> scalar A loads)
    mma_gemm<128, 0, false><<<dim3(4096 / 128, (MROWS + 127) / 128), 256>>>(
        r_fun, p_fun, N_R, MROWS, 4096, FUN_IN, FUN_IN,
        W_fun1, b_fun1, h_fun, 4096, 0, 0, 0);

    // G2: sigmoid(h_att @ W_att2 + b) -> e[:, 0:256] and d_out e_r/e_p
    mma_gemm<64, 1, true><<<dim3(256 / 128, (MROWS + 63) / 64), 256>>>(
        h_att, h_att, MROWS, MROWS, 256, 2048, 2048,
        W_att2, b_att2, 0, 0, e, out, 0);

    // G4: sigmoid(h_fun @ W_fun2 + b) -> e[:, 256:512] and d_out e_r/e_p
    mma_gemm<64, 1, true><<<dim3(256 / 128, (MROWS + 63) / 64), 256>>>(
        h_fun, h_fun, MROWS, MROWS, 256, 4096, 4096,
        W_fun2, b_fun2, 0, 0, e, out, 256);

    // pair head
    cudaFuncSetAttribute(pair_kernel,
        cudaFuncAttributeMaxDynamicSharedMemorySize, SM_TOTAL * 4);
    pair_kernel<<<NB, 256, SM_TOTAL * 4>>>(
        e, idx, conv1w, conv1b, conv2w, conv2b, W_out, b_out, out);
}

// round 7
// speedup vs baseline: 2.2173x; 1.4805x over previous
#include <cuda_runtime.h>
#include <math.h>
#include <stdint.h>

// ---------------- problem constants ----------------
#define N_R     2000
#define N_P     1512
#define MROWS   3512            // N_R + N_P
#define SIZE_R  3000
#define FUN_IN  5603
#define NB      8192            // batch of pairs
#define PROTEIN 1512

// d_out layout: e_r [2000,512] | e_p [1512,512] | output [8192,2] | flat [8192,8192]
#define E_P_OFF   1024000
#define OUT_OFF   1798144
#define FLAT_OFF  1814528

#define SPLITK 4

// ---------------- device scratch (no allocs allowed) ----------------
__device__ float g_h_att[MROWS * 2048];
__device__ float g_h_fun[MROWS * 4096];
__device__ float g_e[MROWS * 512];
__device__ float g_part[SPLITK * MROWS * 256];

// ---------------- helpers ----------------
typedef unsigned long long ull;

__device__ __forceinline__ void mma_tf32(float c[4],
    uint32_t a0, uint32_t a1, uint32_t a2, uint32_t a3,
    uint32_t b0, uint32_t b1)
{
    asm volatile(
        "mma.sync.aligned.m16n8k8.row.col.f32.tf32.tf32.f32 "
        "{%0,%1,%2,%3}, {%4,%5,%6,%7}, {%8,%9}, {%0,%1,%2,%3};\n"
        : "+f"(c[0]), "+f"(c[1]), "+f"(c[2]), "+f"(c[3])
        : "r"(a0), "r"(a1), "r"(a2), "r"(a3), "r"(b0), "r"(b1));
}

__device__ __forceinline__ void cp16(uint32_t dst, const void* src, int srcBytes) {
    asm volatile("cp.async.cg.shared.global [%0], [%1], 16, %2;\n"
                 :: "r"(dst), "l"(src), "r"(srcBytes));
}
__device__ __forceinline__ void cp4(uint32_t dst, const void* src, int srcBytes) {
    asm volatile("cp.async.ca.shared.global [%0], [%1], 4, %2;\n"
                 :: "r"(dst), "l"(src), "r"(srcBytes));
}
__device__ __forceinline__ void cp_commit() {
    asm volatile("cp.async.commit_group;\n" ::);
}
template<int W> __device__ __forceinline__ void cp_wait() {
    asm volatile("cp.async.wait_group %0;\n" :: "n"(W));
}

__device__ __forceinline__ ull pk(float lo, float hi) {
    ull r; asm("mov.b64 %0, {%1, %2};" : "=l"(r) : "f"(lo), "f"(hi)); return r;
}
__device__ __forceinline__ void upk(ull v, float& lo, float& hi) {
    asm("mov.b64 {%0, %1}, %2;" : "=f"(lo), "=f"(hi) : "l"(v));
}
__device__ __forceinline__ ull fma2(ull a, ull b, ull c) {
    ull d; asm("fma.rn.f32x2 %0, %1, %2, %3;" : "=l"(d) : "l"(a), "l"(b), "l"(c)); return d;
}

// ---------------- TF32 tensor-core GEMM, cp.async double-buffered ----------------
// A rows: row < split -> A0[row], else A1[row-split], stride lda.
// MODE 0: gelu(exact) -> C[r*ldc + c], full K.
// MODE 2: raw partial -> C + blockIdx.z*M*256, K slice [z*ksl, min(K,(z+1)*ksl)).
// CTA tile: BM x 128, BK=16, 256 threads = 8 warps (2x4), warp tile (BM/2) x 32.
template<int BM, int MODE, bool ALIGNED>
__global__ void __launch_bounds__(256) mma_gemm(
    const float* __restrict__ A0, const float* __restrict__ A1, int split,
    int M, int N, int K, int lda,
    const float* __restrict__ B, const float* __restrict__ bias,
    float* __restrict__ C, int ldc, int ksl)
{
    constexpr int BN = 128;
    constexpr int BK = 16;
    constexpr int MT = BM / 32;
    constexpr int AF = (BM * BK) / (4 * 256);

    __shared__ uint32_t As[2][BM][20];
    __shared__ uint32_t Bs[2][BK][136];

    const int tid  = threadIdx.x;
    const int lane = tid & 31;
    const int warp = tid >> 5;
    const int wr = warp & 1;
    const int wc = warp >> 1;
    const int g = lane >> 2;
    const int t = lane & 3;

    const int rowBase = blockIdx.y * BM;
    const int colBase = blockIdx.x * BN;
    const int wm = wr * (BM / 2);
    const int wn = wc * 32;

    int kbeg = 0, kend = K;
    if (MODE == 2) { kbeg = blockIdx.z * ksl; kend = min(K, kbeg + ksl); }
    float* Cp = C;
    if (MODE == 2) Cp = C + (size_t)blockIdx.z * M * 256;

    float acc[MT][4][4];
#pragma unroll
    for (int i = 0; i < MT; i++)
#pragma unroll
        for (int j = 0; j < 4; j++)
#pragma unroll
            for (int q = 0; q < 4; q++) acc[i][j][q] = 0.0f;

    const float* Arow[AF];
#pragma unroll
    for (int i = 0; i < AF; i++) {
        int f = tid + i * 256;
        int m = f >> 2;
        int row = rowBase + m;
        Arow[i] = 0;
        if (row < M)
            Arow[i] = (row < split) ? (A0 + (size_t)row * lda)
                                    : (A1 + (size_t)(row - split) * lda);
    }

    const uint32_t AsAddr = (uint32_t)__cvta_generic_to_shared(&As[0][0][0]);
    const uint32_t BsAddr = (uint32_t)__cvta_generic_to_shared(&Bs[0][0][0]);

    const int nIter = (kend - kbeg + BK - 1) / BK;

    // issue stage loads for tile 'it' into buffer 'buf'
    auto issueTile = [&](int it, int buf) {
        int k0 = kbeg + it * BK;
#pragma unroll
        for (int i = 0; i < AF; i++) {
            int f = tid + i * 256;
            int m = f >> 2;
            int kq = f & 3;
            int k = k0 + kq * 4;
            uint32_t dst = AsAddr + (uint32_t)(((buf * BM + m) * 20 + kq * 4) * 4);
            if (ALIGNED) {
                int bytes = 0;
                if (Arow[i]) { bytes = (kend - k) * 4; bytes = bytes < 0 ? 0 : (bytes > 16 ? 16 : bytes); }
                cp16(dst, Arow[i] ? (Arow[i] + k) : A0, bytes);
            } else {
#pragma unroll
                for (int j = 0; j < 4; j++) {
                    int bytes = (Arow[i] && (k + j) < kend) ? 4 : 0;
                    cp4(dst + 4 * j, Arow[i] ? (Arow[i] + k + j) : A0, bytes);
                }
            }
        }
#pragma unroll
        for (int i = 0; i < 2; i++) {
            int f = tid + i * 256;
            int kk = f >> 5;
            int nq = f & 31;
            int krow = k0 + kk;
            uint32_t dst = BsAddr + (uint32_t)(((buf * BK + kk) * 136 + nq * 4) * 4);
            int kc = krow < K - 1 ? krow : K - 1;
            const float* src = B + (size_t)kc * N + colBase + nq * 4;
            cp16(dst, src, krow < kend ? 16 : 0);
        }
        cp_commit();
    };

    issueTile(0, 0);

    for (int it = 0; it < nIter; it++) {
        int buf = it & 1;
        if (it + 1 < nIter) { issueTile(it + 1, buf ^ 1); cp_wait<1>(); }
        else                { cp_wait<0>(); }
        __syncthreads();

#pragma unroll
        for (int ks = 0; ks < 2; ks++) {
            uint32_t afr[MT][4];
            uint32_t bfr[4][2];
#pragma unroll
            for (int mt = 0; mt < MT; mt++) {
                int r0 = wm + mt * 16 + g;
                afr[mt][0] = As[buf][r0][ks * 8 + t];
                afr[mt][1] = As[buf][r0 + 8][ks * 8 + t];
                afr[mt][2] = As[buf][r0][ks * 8 + t + 4];
                afr[mt][3] = As[buf][r0 + 8][ks * 8 + t + 4];
            }
#pragma unroll
            for (int nt = 0; nt < 4; nt++) {
                int c0 = wn + nt * 8 + g;
                bfr[nt][0] = Bs[buf][ks * 8 + t][c0];
                bfr[nt][1] = Bs[buf][ks * 8 + t + 4][c0];
            }
#pragma unroll
            for (int mt = 0; mt < MT; mt++)
#pragma unroll
                for (int nt = 0; nt < 4; nt++)
                    mma_tf32(acc[mt][nt],
                             afr[mt][0], afr[mt][1], afr[mt][2], afr[mt][3],
                             bfr[nt][0], bfr[nt][1]);
        }
        __syncthreads();
    }

    // ---- epilogue ----
#pragma unroll
    for (int mt = 0; mt < MT; mt++) {
#pragma unroll
        for (int rh = 0; rh < 2; rh++) {
            int r = rowBase + wm + mt * 16 + g + rh * 8;
            if (r >= M) continue;
#pragma unroll
            for (int nt = 0; nt < 4; nt++) {
#pragma unroll
                for (int cj = 0; cj < 2; cj++) {
                    int c = colBase + wn + nt * 8 + 2 * t + cj;
                    if (c >= N) continue;
                    float v = acc[mt][nt][rh * 2 + cj];
                    if (MODE == 0) {
                        v += bias[c];
                        v = 0.5f * v * (1.0f + erff(v * 0.70710678118654752f));
                        C[(size_t)r * ldc + c] = v;
                    } else {
                        Cp[(size_t)r * 256 + c] = v;
                    }
                }
            }
        }
    }
}

// ---------------- split-K reduce + bias + sigmoid + scatter ----------------
__global__ void __launch_bounds__(256) splitk_epilogue(
    const float* __restrict__ part, const float* __restrict__ bias,
    float* __restrict__ ebuf, float* __restrict__ dout, int ecol)
{
    int i = blockIdx.x * 256 + threadIdx.x;       // over MROWS*256
    int r = i >> 8;
    int c = i & 255;
    if (r >= MROWS) return;
    float v = part[i];
#pragma unroll
    for (int s = 1; s < SPLITK; s++) v += part[i + (size_t)s * MROWS * 256];
    v = 1.0f / (1.0f + expf(-(v + bias[c])));
    ebuf[(size_t)r * 512 + ecol + c] = v;
    if (r < N_R)
        dout[(size_t)r * 512 + ecol + c] = v;
    else
        dout[(size_t)E_P_OFF + (size_t)(r - N_R) * 512 + ecol + c] = v;
}

// ---------------- pair kernel ----------------
#define SM_XP    0
#define SM_H1P   3120
#define SM_SW2   (3120 + 8448)
#define SM_SW1   (3120 + 8448 + 7680)
#define SM_BRED  (3120 + 8448 + 7680 + 240)
#define SM_TOTAL (3120 + 8448 + 7680 + 240 + 16)

template<int S, int RR, int IH>
__device__ __forceinline__ void combo(
    ull accp[2][2][4], const ull wp[2][2][5], const ull hp[2][11])
{
#pragma unroll
    for (int jp = 0; jp < 4; jp++)
#pragma unroll
        for (int kw = 0; kw < 5; kw++) {
            accp[0][RR][jp] = fma2(wp[0][S][kw], hp[IH][2 * jp + kw], accp[0][RR][jp]);
            accp[1][RR][jp] = fma2(wp[1][S][kw], hp[IH][2 * jp + kw], accp[1][RR][jp]);
        }
}

__global__ void __launch_bounds__(256) pair_kernel(
    const float* __restrict__ e, const int* __restrict__ idx,
    const float* __restrict__ w1, const float* __restrict__ b1,
    const float* __restrict__ w2, const float* __restrict__ b2,
    const float* __restrict__ Wout, const float* __restrict__ bout,
    float* __restrict__ dout)
{
    extern __shared__ float sm[];
    float* xp   = sm + SM_XP;    // [6][520]
    float* h1p  = sm + SM_H1P;   // [16][2][264]
    float* sw2  = sm + SM_SW2;   // [32][16][15]
    float* sw1  = sm + SM_SW1;   // [16][15]
    float* bred = sm + SM_BRED;  // [16]

    const int tid = threadIdx.x;
    const int b = blockIdx.x;

    const int iv = idx[b];
    const int rno = iv / PROTEIN;
    const int pno = iv % PROTEIN;
    const float* er = e + (size_t)rno * 512;
    const float* ep = e + (size_t)(N_R + pno) * 512;

    for (int i = tid; i < 6 * 520; i += 256) xp[i] = 0.0f;
    for (int i = tid; i < 16 * 2 * 264; i += 256) h1p[i] = 0.0f;
    for (int i = tid; i < 240; i += 256) sw1[i] = w1[i];
    for (int i = tid; i < 7680; i += 256) sw2[i] = w2[i];
    for (int w = tid; w < 512; w += 256) {
        xp[2 * 520 + 4 + w] = er[w];
        xp[3 * 520 + 4 + w] = ep[w];
    }
    __syncthreads();

    // conv1 + leaky + avgpool
    for (int id = tid; id < 16 * 2 * 256; id += 256) {
        int c  = id >> 9;
        int rm = id & 511;
        int ph = rm >> 8;
        int pw = rm & 255;
        float wv[15];
#pragma unroll
        for (int q = 0; q < 15; q++) wv[q] = sw1[c * 15 + q];
        float bb = b1[c];
        float sum = 0.0f;
#pragma unroll
        for (int oh2 = 0; oh2 < 2; oh2++) {
#pragma unroll
            for (int ow2 = 0; ow2 < 2; ow2++) {
                int oh = 2 * ph + oh2;
                int ow = 2 * pw + ow2;
                float v = bb;
#pragma unroll
                for (int kh = 0; kh < 3; kh++) {
                    const float* xr = xp + (oh + kh) * 520 + (ow + 2);
#pragma unroll
                    for (int kw = 0; kw < 5; kw++)
                        v = fmaf(wv[kh * 5 + kw], xr[kw], v);
                }
                sum += (v >= 0.0f) ? v : 0.01f * v;
            }
        }
        h1p[(c * 2 + ph) * 264 + 4 + pw] = 0.25f * sum;
    }
    __syncthreads();

    // conv2 (f32x2 packed) + leaky + maxpool + tanh + flat + W_out dot
    float a0 = 0.0f, a1 = 0.0f;

    for (int tt = 0; tt < 4; tt++) {
        int task = tt * 256 + tid;
        int ocp = task >> 6;
        int ph  = (task >> 5) & 1;
        int pwg = task & 31;
        int oc0 = ocp * 2;
        int w0 = pwg * 8;

        ull accp[2][2][4];
#pragma unroll
        for (int o = 0; o < 2; o++)
#pragma unroll
            for (int r = 0; r < 2; r++)
#pragma unroll
                for (int jp = 0; jp < 4; jp++) accp[o][r][jp] = 0ull;

        const int khA = ph ? 0 : 1;   // needed kh rows: {khA, khA+1}

        for (int ic = 0; ic < 16; ic++) {
            // load 2 pooled rows, pre-pack adjacent pairs
            ull hp[2][11];
#pragma unroll
            for (int ih = 0; ih < 2; ih++) {
                const float* row = h1p + (ic * 2 + ih) * 264;
                float hv[16];
                float4 q0 = *(const float4*)(row + w0);
                float4 q1 = *(const float4*)(row + w0 + 4);
                float4 q2 = *(const float4*)(row + w0 + 8);
                float4 q3 = *(const float4*)(row + w0 + 12);
                hv[0]=q0.x; hv[1]=q0.y; hv[2]=q0.z; hv[3]=q0.w;
                hv[4]=q1.x; hv[5]=q1.y; hv[6]=q1.z; hv[7]=q1.w;
                hv[8]=q2.x; hv[9]=q2.y; hv[10]=q2.z; hv[11]=q2.w;
                hv[12]=q3.x; hv[13]=q3.y; hv[14]=q3.z; hv[15]=q3.w;
#pragma unroll
                for (int m = 0; m < 11; m++) hp[ih][m] = pk(hv[2 + m], hv[3 + m]);
            }
            // packed broadcast weights for the 2 needed kh rows
            ull wp[2][2][5];
#pragma unroll
            for (int o = 0; o < 2; o++)
#pragma unroll
                for (int s = 0; s < 2; s++)
#pragma unroll
                    for (int kw = 0; kw < 5; kw++) {
                        float w = sw2[((oc0 + o) * 16 + ic) * 15 + (khA + s) * 5 + kw];
                        wp[o][s][kw] = pk(w, w);
                    }

            if (ph == 0) {
                combo<1, 0, 0>(accp, wp, hp);   // kh=2, rr=0, ih=0
                combo<0, 1, 0>(accp, wp, hp);   // kh=1, rr=1, ih=0
                combo<1, 1, 1>(accp, wp, hp);   // kh=2, rr=1, ih=1
            } else {
                combo<0, 0, 0>(accp, wp, hp);   // kh=0, rr=0, ih=0
                combo<1, 0, 1>(accp, wp, hp);   // kh=1, rr=0, ih=1
                combo<0, 1, 1>(accp, wp, hp);   // kh=0, rr=1, ih=1
            }
        }

        // epilogue: bias -> leaky -> 2x2 maxpool -> tanh; float4 flat store; W_out dot
#pragma unroll
        for (int o = 0; o < 2; o++) {
            int oc = oc0 + o;
            float bb = b2[oc];
            int fibase = oc * 256 + ph * 128 + pwg * 4;
            float4 fv4;
            float fvs[4];
#pragma unroll
            for (int jp = 0; jp < 4; jp++) {
                float v00, v01, v10, v11;
                upk(accp[o][0][jp], v00, v01);
                upk(accp[o][1][jp], v10, v11);
                v00 += bb; v01 += bb; v10 += bb; v11 += bb;
                v00 = (v00 >= 0.0f) ? v00 : 0.01f * v00;
                v01 = (v01 >= 0.0f) ? v01 : 0.01f * v01;
                v10 = (v10 >= 0.0f) ? v10 : 0.01f * v10;
                v11 = (v11 >= 0.0f) ? v11 : 0.01f * v11;
                float m = fmaxf(fmaxf(v00, v01), fmaxf(v10, v11));
                float fv = tanhf(m);
                fvs[jp] = fv;
                int fi = fibase + jp;
                a0 = fmaf(fv, __ldg(&Wout[2 * fi]), a0);
                a1 = fmaf(fv, __ldg(&Wout[2 * fi + 1]), a1);
            }
            fv4.x = fvs[0]; fv4.y = fvs[1]; fv4.z = fvs[2]; fv4.w = fvs[3];
            *(float4*)(dout + (size_t)FLAT_OFF + (size_t)b * 8192 + fibase) = fv4;
        }
    }

#pragma unroll
    for (int off = 16; off > 0; off >>= 1) {
        a0 += __shfl_down_sync(0xFFFFFFFFu, a0, off);
        a1 += __shfl_down_sync(0xFFFFFFFFu, a1, off);
    }
    if ((tid & 31) == 0) {
        bred[(tid >> 5) * 2 + 0] = a0;
        bred[(tid >> 5) * 2 + 1] = a1;
    }
    __syncthreads();
    if (tid == 0) {
        float s0 = bout[0], s1 = bout[1];
#pragma unroll
        for (int w = 0; w < 8; w++) { s0 += bred[2 * w]; s1 += bred[2 * w + 1]; }
        dout[(size_t)OUT_OFF + (size_t)b * 2 + 0] = s0;
        dout[(size_t)OUT_OFF + (size_t)b * 2 + 1] = s1;
    }
}

// ---------------- launcher ----------------
extern "C" void kernel_launch(void* const* d_in, const int* in_sizes, int n_in,
                              void* d_out, int out_size)
{
    const float* r_att  = (const float*)d_in[0];
    const float* p_att  = (const float*)d_in[1];
    const float* r_fun  = (const float*)d_in[2];
    const float* p_fun  = (const float*)d_in[3];
    const int*   idx    = (const int*)  d_in[4];
    const float* W_att1 = (const float*)d_in[5];
    const float* b_att1 = (const float*)d_in[6];
    const float* W_att2 = (const float*)d_in[7];
    const float* b_att2 = (const float*)d_in[8];
    const float* W_fun1 = (const float*)d_in[9];
    const float* b_fun1 = (const float*)d_in[10];
    const float* W_fun2 = (const float*)d_in[11];
    const float* b_fun2 = (const float*)d_in[12];
    const float* conv1w = (const float*)d_in[13];
    const float* conv1b = (const float*)d_in[14];
    const float* conv2w = (const float*)d_in[15];
    const float* conv2b = (const float*)d_in[16];
    const float* W_out  = (const float*)d_in[17];
    const float* b_out  = (const float*)d_in[18];
    float* out = (float*)d_out;

    float *h_att, *h_fun, *e, *part;
    cudaGetSymbolAddress((void**)&h_att, g_h_att);
    cudaGetSymbolAddress((void**)&h_fun, g_h_fun);
    cudaGetSymbolAddress((void**)&e,     g_e);
    cudaGetSymbolAddress((void**)&part,  g_part);

    const int epBlocks = (MROWS * 256 + 255) / 256;

    // G1: gelu(att @ W_att1 + b) -> h_att [3512 x 2048], K=3000 (aligned)
    mma_gemm<128, 0, true><<<dim3(2048 / 128, (MROWS + 127) / 128), 256>>>(
        r_att, p_att, N_R, MROWS, 2048, SIZE_R, SIZE_R,
        W_att1, b_att1, h_att, 2048, 0);

    // G2 split-K: h_att @ W_att2 partials -> part, then reduce+sigmoid
    mma_gemm<64, 2, true><<<dim3(2, (MROWS + 63) / 64, SPLITK), 256>>>(
        h_att, h_att, MROWS, MROWS, 256, 2048, 2048,
        W_att2, 0, part, 256, 512);
    splitk_epilogue<<<epBlocks, 256>>>(part, b_att2, e, out, 0);

    // G3: gelu(fun @ W_fun1 + b) -> h_fun [3512 x 4096], K=5603 (odd lda)
    mma_gemm<128, 0, false><<<dim3(4096 / 128, (MROWS + 127) / 128), 256>>>(
        r_fun, p_fun, N_R, MROWS, 4096, FUN_IN, FUN_IN,
        W_fun1, b_fun1, h_fun, 4096, 0);

    // G4 split-K: h_fun @ W_fun2 partials -> part, then reduce+sigmoid
    mma_gemm<64, 2, true><<<dim3(2, (MROWS + 63) / 64, SPLITK), 256>>>(
        h_fun, h_fun, MROWS, MROWS, 256, 4096, 4096,
        W_fun2, 0, part, 256, 1024);
    splitk_epilogue<<<epBlocks, 256>>>(part, b_fun2, e, out, 256);

    // pair head
    cudaFuncSetAttribute(pair_kernel,
        cudaFuncAttributeMaxDynamicSharedMemorySize, SM_TOTAL * 4);
    pair_kernel<<<NB, 256, SM_TOTAL * 4>>>(
        e, idx, conv1w, conv1b, conv2w, conv2b, W_out, b_out, out);
}